// round 1
// baseline (speedup 1.0000x reference)
#include <cuda_runtime.h>

// LightGCN layer: two independent gather-scale-scatter-sum relations.
//   h_item[ui_dst] += norm_ui * user_feat[ui_src]   (E=2M, D=64)
//   h_user[iu_dst] += norm_iu * item_feat[iu_src]   (E=2M, D=64)
// Output layout: [h_user (n_users*64) | h_item (n_items*64)]

__global__ void zero_kernel(float4* __restrict__ out, int n4) {
    int i = blockIdx.x * blockDim.x + threadIdx.x;
    if (i < n4) out[i] = make_float4(0.f, 0.f, 0.f, 0.f);
}

// 16 threads per edge; thread c owns float4 chunk c (64 floats = 16 chunks).
// Group leader (chunk 0) loads src/dst/norm, broadcast via shfl within warp half.
__global__ void scatter_kernel(const float4* __restrict__ feat,
                               const float*  __restrict__ norm,
                               const int*    __restrict__ src,
                               const int*    __restrict__ dst,
                               float*        __restrict__ out,
                               int n_edges) {
    int gid = blockIdx.x * blockDim.x + threadIdx.x;
    int e = gid >> 4;
    if (e >= n_edges) return;
    int c = gid & 15;

    int lane   = threadIdx.x & 31;
    int leader = lane & 16;          // 0 for lanes 0-15, 16 for lanes 16-31

    int s = 0, d = 0;
    float w = 0.f;
    if ((lane & 15) == 0) {
        s = src[e];
        d = dst[e];
        w = norm[e];
    }
    s = __shfl_sync(0xffffffffu, s, leader);
    d = __shfl_sync(0xffffffffu, d, leader);
    w = __shfl_sync(0xffffffffu, w, leader);

    float4 v = feat[(size_t)s * 16 + c];

    float* p = out + ((size_t)d << 6) + (c << 2);
    // Vectorized no-return global reduction (sm_90+): one L2 atomic op per 16B.
    asm volatile("red.global.add.v4.f32 [%0], {%1, %2, %3, %4};"
                 :: "l"(p), "f"(v.x * w), "f"(v.y * w), "f"(v.z * w), "f"(v.w * w)
                 : "memory");
}

extern "C" void kernel_launch(void* const* d_in, const int* in_sizes, int n_in,
                              void* d_out, int out_size) {
    const float* user_feat = (const float*)d_in[0];
    const float* item_feat = (const float*)d_in[1];
    const float* norm_ui   = (const float*)d_in[2];
    const float* norm_iu   = (const float*)d_in[3];
    const int*   ui_src    = (const int*)d_in[4];
    const int*   ui_dst    = (const int*)d_in[5];
    const int*   iu_src    = (const int*)d_in[6];
    const int*   iu_dst    = (const int*)d_in[7];

    float* out = (float*)d_out;

    const int D = 64;
    int n_users = in_sizes[0] / D;
    int E_ui = in_sizes[4];
    int E_iu = in_sizes[6];

    // 1. Zero the output (harness poisons it with 0xAA).
    int n4 = out_size / 4;
    zero_kernel<<<(n4 + 255) / 256, 256>>>((float4*)out, n4);

    // 2. h_user: gather item_feat[iu_src] * norm_iu, scatter-add to out[iu_dst].
    {
        long long threads = (long long)E_iu * 16;
        int blocks = (int)((threads + 255) / 256);
        scatter_kernel<<<blocks, 256>>>((const float4*)item_feat, norm_iu,
                                        iu_src, iu_dst, out, E_iu);
    }

    // 3. h_item: gather user_feat[ui_src] * norm_ui, scatter-add to out+n_users*64.
    {
        long long threads = (long long)E_ui * 16;
        int blocks = (int)((threads + 255) / 256);
        scatter_kernel<<<blocks, 256>>>((const float4*)user_feat, norm_ui,
                                        ui_src, ui_dst,
                                        out + (size_t)n_users * D, E_ui);
    }
}

// round 2
// speedup vs baseline: 1.4065x; 1.4065x over previous
#include <cuda_runtime.h>

// LightGCN layer, gather-form:
//   h_item[d] = sum_{e: ui_dst[e]=d} norm_ui[e] * user_feat[ui_src[e]]
//   h_user[d] = sum_{e: iu_dst[e]=d} norm_iu[e] * item_feat[iu_src[e]]
// Output layout: [h_user (n_users*64) | h_item (n_items*64)]
//
// Strategy: bucket all 4M edges by destination (CSR) into device scratch,
// then one warp per output row accumulates in registers -> single store.
// Rows [0, n_items) are item destinations (relation ui, feat = user_feat),
// rows [n_items, n_items+n_users) are user destinations (relation iu).

#define MAX_ROWS  150000
#define MAX_EDGES 4000000
#define SCAN_BLK  1024

__device__ int  g_counts [MAX_ROWS + 1];
__device__ int  g_offsets[MAX_ROWS + 1];
__device__ int  g_cursor [MAX_ROWS];
__device__ int  g_partials[(MAX_ROWS + SCAN_BLK - 1) / SCAN_BLK + 1];
__device__ int2 g_edges  [MAX_EDGES];

// ---------------------------------------------------------------- zero counts
__global__ void k_zero_counts(int n) {
    int i = blockIdx.x * blockDim.x + threadIdx.x;
    if (i <= n) g_counts[i] = 0;
}

// ---------------------------------------------------------------- histogram
__global__ void k_hist(const int* __restrict__ ui_dst,
                       const int* __restrict__ iu_dst,
                       int E_ui, int E_total, int n_items) {
    int e = blockIdx.x * blockDim.x + threadIdx.x;
    if (e >= E_total) return;
    int d = (e < E_ui) ? ui_dst[e] : (n_items + iu_dst[e - E_ui]);
    atomicAdd(&g_counts[d], 1);
}

// ---------------------------------------------------------------- scan pass 1: block sums
__global__ void k_scan_blocksums(int n) {
    __shared__ int sh[SCAN_BLK];
    int i = blockIdx.x * SCAN_BLK + threadIdx.x;
    sh[threadIdx.x] = (i < n) ? g_counts[i] : 0;
    __syncthreads();
    for (int off = SCAN_BLK / 2; off > 0; off >>= 1) {
        if (threadIdx.x < off) sh[threadIdx.x] += sh[threadIdx.x + off];
        __syncthreads();
    }
    if (threadIdx.x == 0) g_partials[blockIdx.x] = sh[0];
}

// ---------------------------------------------------------------- scan pass 2: scan of partials (1 block)
__global__ void k_scan_partials(int nb) {
    __shared__ int sh[SCAN_BLK];
    int tid = threadIdx.x;
    int v = (tid < nb) ? g_partials[tid] : 0;
    sh[tid] = v;
    __syncthreads();
    for (int off = 1; off < SCAN_BLK; off <<= 1) {
        int t = (tid >= off) ? sh[tid - off] : 0;
        __syncthreads();
        sh[tid] += t;
        __syncthreads();
    }
    if (tid < nb) g_partials[tid] = sh[tid] - v;  // exclusive
}

// ---------------------------------------------------------------- scan pass 3: final offsets + cursor
__global__ void k_scan_final(int n) {
    __shared__ int sh[SCAN_BLK];
    int tid = threadIdx.x;
    int i = blockIdx.x * SCAN_BLK + tid;
    int v = (i < n) ? g_counts[i] : 0;
    sh[tid] = v;
    __syncthreads();
    for (int off = 1; off < SCAN_BLK; off <<= 1) {
        int t = (tid >= off) ? sh[tid - off] : 0;
        __syncthreads();
        sh[tid] += t;
        __syncthreads();
    }
    if (i < n) {
        int base = g_partials[blockIdx.x];
        int excl = base + sh[tid] - v;
        g_offsets[i] = excl;
        g_cursor[i]  = excl;
        if (i == n - 1) g_offsets[n] = excl + v;
    }
}

// ---------------------------------------------------------------- reorder edges into buckets
__global__ void k_reorder(const int*   __restrict__ ui_src,
                          const int*   __restrict__ ui_dst,
                          const float* __restrict__ norm_ui,
                          const int*   __restrict__ iu_src,
                          const int*   __restrict__ iu_dst,
                          const float* __restrict__ norm_iu,
                          int E_ui, int E_total, int n_items) {
    int e = blockIdx.x * blockDim.x + threadIdx.x;
    if (e >= E_total) return;
    int d, s; float w;
    if (e < E_ui) {
        d = ui_dst[e];
        s = ui_src[e];
        w = norm_ui[e];
    } else {
        int e2 = e - E_ui;
        d = n_items + iu_dst[e2];
        s = iu_src[e2];
        w = norm_iu[e2];
    }
    int pos = atomicAdd(&g_cursor[d], 1);
    g_edges[pos] = make_int2(s, __float_as_int(w));
}

// ---------------------------------------------------------------- gather: one warp per output row
__global__ void __launch_bounds__(256)
k_gather(const float4* __restrict__ user_feat,
         const float4* __restrict__ item_feat,
         float* __restrict__ out,
         int n_items, int n_users) {
    int gid  = blockIdx.x * blockDim.x + threadIdx.x;
    int row  = gid >> 5;
    int n_total = n_items + n_users;
    if (row >= n_total) return;

    int lane = threadIdx.x & 31;
    int half = lane >> 4;       // 0: even edges, 1: odd edges
    int c    = lane & 15;       // float4 chunk within the 64-float row

    const float4* feat;
    float4* orow;
    if (row < n_items) {
        feat = user_feat;                                   // relation ui -> items
        orow = (float4*)(out + ((size_t)(n_users + row) << 6));
    } else {
        feat = item_feat;                                   // relation iu -> users
        orow = (float4*)(out + ((size_t)(row - n_items) << 6));
    }

    int start = g_offsets[row];
    int end   = g_offsets[row + 1];

    float4 acc = make_float4(0.f, 0.f, 0.f, 0.f);

    for (int base = start; base < end; base += 32) {
        int idx = base + lane;
        int2 ent = (idx < end) ? g_edges[idx] : make_int2(0, 0);
        int cnt = min(32, end - base);
        #pragma unroll 4
        for (int j = 0; j < cnt; j += 2) {
            int jj = j + half;                  // lane's entry index within chunk
            int   s = __shfl_sync(0xffffffffu, ent.x, jj);
            float w = __int_as_float(__shfl_sync(0xffffffffu, ent.y, jj));
            // jj == cnt (odd tail) hits a padded {0,0} entry -> w = 0 -> no-op
            float4 v = feat[(size_t)s * 16 + c];
            acc.x += v.x * w;
            acc.y += v.y * w;
            acc.z += v.z * w;
            acc.w += v.w * w;
        }
    }

    // combine the two half-warp partials (lane c += lane c+16)
    acc.x += __shfl_down_sync(0xffffffffu, acc.x, 16);
    acc.y += __shfl_down_sync(0xffffffffu, acc.y, 16);
    acc.z += __shfl_down_sync(0xffffffffu, acc.z, 16);
    acc.w += __shfl_down_sync(0xffffffffu, acc.w, 16);

    if (half == 0) orow[c] = acc;
}

// ---------------------------------------------------------------- launch
extern "C" void kernel_launch(void* const* d_in, const int* in_sizes, int n_in,
                              void* d_out, int out_size) {
    const float* user_feat = (const float*)d_in[0];
    const float* item_feat = (const float*)d_in[1];
    const float* norm_ui   = (const float*)d_in[2];
    const float* norm_iu   = (const float*)d_in[3];
    const int*   ui_src    = (const int*)d_in[4];
    const int*   ui_dst    = (const int*)d_in[5];
    const int*   iu_src    = (const int*)d_in[6];
    const int*   iu_dst    = (const int*)d_in[7];

    float* out = (float*)d_out;

    const int D = 64;
    int n_users = in_sizes[0] / D;
    int n_items = in_sizes[1] / D;
    int E_ui    = in_sizes[4];
    int E_iu    = in_sizes[6];
    int E_total = E_ui + E_iu;
    int n_total = n_items + n_users;

    // 1. zero counts
    k_zero_counts<<<(n_total + 1 + 255) / 256, 256>>>(n_total);

    // 2. histogram over all 4M edges (row space: [items | users])
    k_hist<<<(E_total + 255) / 256, 256>>>(ui_dst, iu_dst, E_ui, E_total, n_items);

    // 3. exclusive scan of counts -> offsets (and cursor copy)
    int nb = (n_total + SCAN_BLK - 1) / SCAN_BLK;
    k_scan_blocksums<<<nb, SCAN_BLK>>>(n_total);
    k_scan_partials<<<1, SCAN_BLK>>>(nb);
    k_scan_final<<<nb, SCAN_BLK>>>(n_total);

    // 4. reorder edges into destination buckets
    k_reorder<<<(E_total + 255) / 256, 256>>>(ui_src, ui_dst, norm_ui,
                                              iu_src, iu_dst, norm_iu,
                                              E_ui, E_total, n_items);

    // 5. gather: one warp per output row, register accumulation, single store
    long long threads = (long long)n_total * 32;
    k_gather<<<(int)((threads + 255) / 256), 256>>>((const float4*)user_feat,
                                                    (const float4*)item_feat,
                                                    out, n_items, n_users);
}

// round 3
// speedup vs baseline: 1.4610x; 1.0387x over previous
#include <cuda_runtime.h>

// LightGCN layer, gather-form with destination-bucketed CSR built on the fly.
//   rows [0, n_items)            : h_item[d] = sum norm_ui * user_feat[ui_src]
//   rows [n_items, n_items+n_us) : h_user[d] = sum norm_iu * item_feat[iu_src]
// Output layout: [h_user (n_users*64) | h_item (n_items*64)]

#define MAX_ROWS  150002
#define MAX_EDGES 4000000
#define SCAN_BLK  1024

__device__ int  g_counts  [MAX_ROWS + 1];
__device__ int  g_offsets [MAX_ROWS + 1];
__device__ int  g_rank    [MAX_EDGES];
__device__ int  g_partials[(MAX_ROWS + SCAN_BLK - 1) / SCAN_BLK + 2];
__device__ int2 g_edges   [MAX_EDGES];

__device__ __forceinline__ int warp_scan_inc(int v) {
    #pragma unroll
    for (int o = 1; o < 32; o <<= 1) {
        int t = __shfl_up_sync(0xffffffffu, v, o);
        if ((threadIdx.x & 31) >= o) v += t;
    }
    return v;
}

// ---------------------------------------------------------------- zero counts
__global__ void k_zero_counts(int n) {
    int i = blockIdx.x * blockDim.x + threadIdx.x;
    if (i <= n) g_counts[i] = 0;
}

// ------------------------------------------- histogram (also records rank)
__global__ void k_hist(const int* __restrict__ ui_dst,
                       const int* __restrict__ iu_dst,
                       int E_ui, int E_total, int n_items) {
    int e = blockIdx.x * blockDim.x + threadIdx.x;
    if (e >= E_total) return;
    int d = (e < E_ui) ? ui_dst[e] : (n_items + iu_dst[e - E_ui]);
    g_rank[e] = atomicAdd(&g_counts[d], 1);   // old count = within-bucket rank
}

// ------------------------------------------- scan pass 1: block sums (shfl)
__global__ void k_scan_blocksums(int n) {
    __shared__ int wsum[32];
    int tid = threadIdx.x;
    int i = blockIdx.x * SCAN_BLK + tid;
    int v = (i < n) ? g_counts[i] : 0;
    #pragma unroll
    for (int o = 16; o > 0; o >>= 1) v += __shfl_down_sync(0xffffffffu, v, o);
    if ((tid & 31) == 0) wsum[tid >> 5] = v;
    __syncthreads();
    if (tid < 32) {
        int s = wsum[tid];
        #pragma unroll
        for (int o = 16; o > 0; o >>= 1) s += __shfl_down_sync(0xffffffffu, s, o);
        if (tid == 0) g_partials[blockIdx.x] = s;
    }
}

// ------------------------------------------- scan pass 2: scan partials (1 blk)
__global__ void k_scan_partials(int nb) {
    __shared__ int wsum[32];
    int tid = threadIdx.x;
    int v = (tid < nb) ? g_partials[tid] : 0;
    int inc = warp_scan_inc(v);
    if ((tid & 31) == 31) wsum[tid >> 5] = inc;
    __syncthreads();
    if (tid < 32) {
        int s = wsum[tid];
        int si = warp_scan_inc(s);
        wsum[tid] = si - s;            // exclusive warp base
    }
    __syncthreads();
    int excl = wsum[tid >> 5] + inc - v;
    if (tid < nb) g_partials[tid] = excl;
}

// ------------------------------------------- scan pass 3: final offsets (shfl)
__global__ void k_scan_final(int n) {
    __shared__ int wsum[32];
    int tid = threadIdx.x;
    int i = blockIdx.x * SCAN_BLK + tid;
    int v = (i < n) ? g_counts[i] : 0;
    int inc = warp_scan_inc(v);
    if ((tid & 31) == 31) wsum[tid >> 5] = inc;
    __syncthreads();
    if (tid < 32) {
        int s = wsum[tid];
        int si = warp_scan_inc(s);
        wsum[tid] = si - s;
    }
    __syncthreads();
    int excl = g_partials[blockIdx.x] + wsum[tid >> 5] + inc - v;
    if (i < n) {
        g_offsets[i] = excl;
        if (i == n - 1) g_offsets[n] = excl + v;
    }
}

// ------------------------------------------- reorder (no atomics: rank known)
__global__ void k_reorder(const int*   __restrict__ ui_src,
                          const int*   __restrict__ ui_dst,
                          const float* __restrict__ norm_ui,
                          const int*   __restrict__ iu_src,
                          const int*   __restrict__ iu_dst,
                          const float* __restrict__ norm_iu,
                          int E_ui, int E_total, int n_items) {
    int e = blockIdx.x * blockDim.x + threadIdx.x;
    if (e >= E_total) return;
    int d, s; float w;
    if (e < E_ui) {
        d = ui_dst[e];
        s = ui_src[e];
        w = norm_ui[e];
    } else {
        int e2 = e - E_ui;
        d = n_items + iu_dst[e2];
        s = iu_src[e2];
        w = norm_iu[e2];
    }
    int pos = g_offsets[d] + g_rank[e];
    g_edges[pos] = make_int2(s, __float_as_int(w));
}

// ------------------------------------------- gather: one warp per output row
__global__ void __launch_bounds__(256)
k_gather(const float4* __restrict__ user_feat,
         const float4* __restrict__ item_feat,
         float* __restrict__ out,
         int n_items, int n_users) {
    int gid = blockIdx.x * blockDim.x + threadIdx.x;
    int row = gid >> 5;
    int n_total = n_items + n_users;
    if (row >= n_total) return;

    int lane = threadIdx.x & 31;
    int half = lane >> 4;        // lanes 0-15: even edges, 16-31: odd edges
    int c    = lane & 15;        // float4 chunk within the 64-float row

    const float4* feat;
    float4* orow;
    if (row < n_items) {
        feat = user_feat;                                    // relation ui -> items
        orow = (float4*)(out + ((size_t)(n_users + row) << 6));
    } else {
        feat = item_feat;                                    // relation iu -> users
        orow = (float4*)(out + ((size_t)(row - n_items) << 6));
    }

    int start = g_offsets[row];
    int end   = g_offsets[row + 1];

    float4 acc = make_float4(0.f, 0.f, 0.f, 0.f);

    for (int base = start; base < end; base += 32) {
        int idx = base + lane;
        int2 ent = (idx < end) ? g_edges[idx] : make_int2(0, 0);
        int entries = min(32, end - base);
        int nsteps  = ((entries + 1) >> 1);   // 2 edges per step
        nsteps = (nsteps + 7) & ~7;           // round to 8 -> unroll-8 MLP
        #pragma unroll 8
        for (int j2 = 0; j2 < nsteps; j2++) {
            int jj = (j2 << 1) + half;
            int   s = __shfl_sync(0xffffffffu, ent.x, jj);
            float w = __int_as_float(__shfl_sync(0xffffffffu, ent.y, jj));
            // padded entries are {0,0}: w=0 no-op, s=0 row stays L1-resident
            float4 v = __ldg(&feat[(size_t)s * 16 + c]);
            acc.x += v.x * w;
            acc.y += v.y * w;
            acc.z += v.z * w;
            acc.w += v.w * w;
        }
    }

    // combine the two half-warp partials (lane c += lane c+16)
    acc.x += __shfl_down_sync(0xffffffffu, acc.x, 16);
    acc.y += __shfl_down_sync(0xffffffffu, acc.y, 16);
    acc.z += __shfl_down_sync(0xffffffffu, acc.z, 16);
    acc.w += __shfl_down_sync(0xffffffffu, acc.w, 16);

    if (half == 0) orow[c] = acc;
}

// ---------------------------------------------------------------- launch
extern "C" void kernel_launch(void* const* d_in, const int* in_sizes, int n_in,
                              void* d_out, int out_size) {
    const float* user_feat = (const float*)d_in[0];
    const float* item_feat = (const float*)d_in[1];
    const float* norm_ui   = (const float*)d_in[2];
    const float* norm_iu   = (const float*)d_in[3];
    const int*   ui_src    = (const int*)d_in[4];
    const int*   ui_dst    = (const int*)d_in[5];
    const int*   iu_src    = (const int*)d_in[6];
    const int*   iu_dst    = (const int*)d_in[7];

    float* out = (float*)d_out;

    const int D = 64;
    int n_users = in_sizes[0] / D;
    int n_items = in_sizes[1] / D;
    int E_ui    = in_sizes[4];
    int E_iu    = in_sizes[6];
    int E_total = E_ui + E_iu;
    int n_total = n_items + n_users;

    // 1. zero counts
    k_zero_counts<<<(n_total + 1 + 255) / 256, 256>>>(n_total);

    // 2. histogram over all edges; records within-bucket rank per edge
    k_hist<<<(E_total + 255) / 256, 256>>>(ui_dst, iu_dst, E_ui, E_total, n_items);

    // 3. exclusive scan of counts -> offsets
    int nb = (n_total + SCAN_BLK - 1) / SCAN_BLK;
    k_scan_blocksums<<<nb, SCAN_BLK>>>(n_total);
    k_scan_partials<<<1, SCAN_BLK>>>(nb);
    k_scan_final<<<nb, SCAN_BLK>>>(n_total);

    // 4. reorder edges into destination buckets (atomic-free)
    k_reorder<<<(E_total + 255) / 256, 256>>>(ui_src, ui_dst, norm_ui,
                                              iu_src, iu_dst, norm_iu,
                                              E_ui, E_total, n_items);

    // 5. gather: one warp per output row, register accumulation, single store
    long long threads = (long long)n_total * 32;
    k_gather<<<(int)((threads + 255) / 256), 256>>>((const float4*)user_feat,
                                                    (const float4*)item_feat,
                                                    out, n_items, n_users);
}

// round 7
// speedup vs baseline: 1.5031x; 1.0288x over previous
#include <cuda_runtime.h>
#include <cuda_fp16.h>

// LightGCN layer, gather-form, destination-bucketed CSR + fp16 feature table.
//   rows [0, n_items)            : h_item[d] = sum norm_ui * user_feat[ui_src]
//   rows [n_items, n_items+n_us) : h_user[d] = sum norm_iu * item_feat[iu_src]
// Output layout: [h_user (n_users*64) | h_item (n_items*64)]
// Combined half feature table: rows [0,n_users) = user, [n_users,+n_items) = item.

#define MAX_ROWS  150002
#define MAX_EDGES 4000000
#define SCAN_BLK  1024
#define D         64

// 16-byte vector of 4 half2 (8 halves) -> single LDG.128 / STG.128.
struct __align__(16) H2x4 { __half2 a, b, c, d; };

__device__ int  g_counts  [MAX_ROWS + 1];
__device__ int  g_offsets [MAX_ROWS + 1];
__device__ int  g_cursor  [MAX_ROWS];
__device__ int  g_partials[(MAX_ROWS + SCAN_BLK - 1) / SCAN_BLK + 2];
__device__ int2 g_edges   [MAX_EDGES];
__device__ H2x4 g_feat_h  [MAX_ROWS * D / 8];   // 8 halves per entry

__device__ __forceinline__ int warp_scan_inc(int v) {
    #pragma unroll
    for (int o = 1; o < 32; o <<= 1) {
        int t = __shfl_up_sync(0xffffffffu, v, o);
        if ((threadIdx.x & 31) >= o) v += t;
    }
    return v;
}

// ------------------------------------------- fp32 -> fp16 table conversion
// Destination g_feat_h is referenced ONLY from device code (a __device__
// symbol's address is not valid as a host-side kernel argument).
// Each thread: 8 floats (2 float4 loads) -> 1 H2x4 (8 halves) store.
__global__ void k_convert(const float4* __restrict__ user,
                          const float4* __restrict__ item,
                          int n8u, int n8total) {
    int i = blockIdx.x * blockDim.x + threadIdx.x;
    if (i >= n8total) return;
    const float4* src = (i < n8u) ? (user + 2 * (size_t)i)
                                  : (item + 2 * (size_t)(i - n8u));
    float4 a = src[0];
    float4 b = src[1];
    H2x4 o;
    o.a = __floats2half2_rn(a.x, a.y);
    o.b = __floats2half2_rn(a.z, a.w);
    o.c = __floats2half2_rn(b.x, b.y);
    o.d = __floats2half2_rn(b.z, b.w);
    g_feat_h[i] = o;
}

// ---------------------------------------------------------------- zero counts
__global__ void k_zero_counts(int n) {
    int i = blockIdx.x * blockDim.x + threadIdx.x;
    if (i <= n) g_counts[i] = 0;
}

// ------------------------------------------- histogram
__global__ void k_hist(const int* __restrict__ ui_dst,
                       const int* __restrict__ iu_dst,
                       int E_ui, int E_total, int n_items) {
    int e = blockIdx.x * blockDim.x + threadIdx.x;
    if (e >= E_total) return;
    int d = (e < E_ui) ? ui_dst[e] : (n_items + iu_dst[e - E_ui]);
    atomicAdd(&g_counts[d], 1);
}

// ------------------------------------------- scan pass 1: block sums (shfl)
__global__ void k_scan_blocksums(int n) {
    __shared__ int wsum[32];
    int tid = threadIdx.x;
    int i = blockIdx.x * SCAN_BLK + tid;
    int v = (i < n) ? g_counts[i] : 0;
    #pragma unroll
    for (int o = 16; o > 0; o >>= 1) v += __shfl_down_sync(0xffffffffu, v, o);
    if ((tid & 31) == 0) wsum[tid >> 5] = v;
    __syncthreads();
    if (tid < 32) {
        int s = wsum[tid];
        #pragma unroll
        for (int o = 16; o > 0; o >>= 1) s += __shfl_down_sync(0xffffffffu, s, o);
        if (tid == 0) g_partials[blockIdx.x] = s;
    }
}

// ------------------------------------------- scan pass 2: scan partials (1 blk)
__global__ void k_scan_partials(int nb) {
    __shared__ int wsum[32];
    int tid = threadIdx.x;
    int v = (tid < nb) ? g_partials[tid] : 0;
    int inc = warp_scan_inc(v);
    if ((tid & 31) == 31) wsum[tid >> 5] = inc;
    __syncthreads();
    if (tid < 32) {
        int s = wsum[tid];
        int si = warp_scan_inc(s);
        wsum[tid] = si - s;
    }
    __syncthreads();
    int excl = wsum[tid >> 5] + inc - v;
    if (tid < nb) g_partials[tid] = excl;
}

// ------------------------------------------- scan pass 3: final offsets + cursor
__global__ void k_scan_final(int n) {
    __shared__ int wsum[32];
    int tid = threadIdx.x;
    int i = blockIdx.x * SCAN_BLK + tid;
    int v = (i < n) ? g_counts[i] : 0;
    int inc = warp_scan_inc(v);
    if ((tid & 31) == 31) wsum[tid >> 5] = inc;
    __syncthreads();
    if (tid < 32) {
        int s = wsum[tid];
        int si = warp_scan_inc(s);
        wsum[tid] = si - s;
    }
    __syncthreads();
    int excl = g_partials[blockIdx.x] + wsum[tid >> 5] + inc - v;
    if (i < n) {
        g_offsets[i] = excl;
        g_cursor[i]  = excl;
        if (i == n - 1) g_offsets[n] = excl + v;
    }
}

// ------------------------------------------- reorder (atomic cursor)
// Stores table-adjusted src: user rows as-is, item rows offset by n_users.
__global__ void k_reorder(const int*   __restrict__ ui_src,
                          const int*   __restrict__ ui_dst,
                          const float* __restrict__ norm_ui,
                          const int*   __restrict__ iu_src,
                          const int*   __restrict__ iu_dst,
                          const float* __restrict__ norm_iu,
                          int E_ui, int E_total, int n_items, int n_users) {
    int e = blockIdx.x * blockDim.x + threadIdx.x;
    if (e >= E_total) return;
    int d, s; float w;
    if (e < E_ui) {
        d = ui_dst[e];           // item row
        s = ui_src[e];           // user feature -> table offset s
        w = norm_ui[e];
    } else {
        int e2 = e - E_ui;
        d = n_items + iu_dst[e2];       // user row
        s = n_users + iu_src[e2];       // item feature -> table offset n_users+s
        w = norm_iu[e2];
    }
    int pos = atomicAdd(&g_cursor[d], 1);
    g_edges[pos] = make_int2(s, __float_as_int(w));
}

// ------------------------------------------- gather: one warp per output row
// 4 edges per warp-step: group = lane>>3 picks the edge, c = lane&7 picks the
// 8-half chunk (16B). fp32 accumulation, 2-level shfl_xor reduction.
__global__ void __launch_bounds__(256)
k_gather(float* __restrict__ out, int n_items, int n_users) {
    int gid = blockIdx.x * blockDim.x + threadIdx.x;
    int row = gid >> 5;
    int n_total = n_items + n_users;
    if (row >= n_total) return;

    int lane  = threadIdx.x & 31;
    int group = lane >> 3;       // which of 4 edges per step
    int c     = lane & 7;        // 16B chunk within the 128B half row

    float* orow;
    if (row < n_items) {
        orow = out + ((size_t)(n_users + row) << 6);   // h_item
    } else {
        orow = out + ((size_t)(row - n_items) << 6);   // h_user
    }

    int start = g_offsets[row];
    int end   = g_offsets[row + 1];

    float acc[8];
    #pragma unroll
    for (int k = 0; k < 8; k++) acc[k] = 0.f;

    for (int base = start; base < end; base += 32) {
        int idx = base + lane;
        int2 ent = (idx < end) ? g_edges[idx] : make_int2(0, 0);
        int entries = min(32, end - base);
        int nsteps = (entries + 3) >> 2;     // 4 edges per step
        nsteps = (nsteps + 3) & ~3;          // round to 4 for unroll MLP
        #pragma unroll 4
        for (int j = 0; j < nsteps; j++) {
            int jj = (j << 2) | group;
            int   s = __shfl_sync(0xffffffffu, ent.x, jj);
            float w = __int_as_float(__shfl_sync(0xffffffffu, ent.y, jj));
            // padded entries are {0,0}: w=0 no-op, s=0 row stays hot
            H2x4 hv = g_feat_h[(size_t)s * 8 + c];
            float2 f0 = __half22float2(hv.a);
            float2 f1 = __half22float2(hv.b);
            float2 f2 = __half22float2(hv.c);
            float2 f3 = __half22float2(hv.d);
            acc[0] += f0.x * w;  acc[1] += f0.y * w;
            acc[2] += f1.x * w;  acc[3] += f1.y * w;
            acc[4] += f2.x * w;  acc[5] += f2.y * w;
            acc[6] += f3.x * w;  acc[7] += f3.y * w;
        }
    }

    // reduce 4 groups -> lanes 0-7
    #pragma unroll
    for (int k = 0; k < 8; k++) {
        acc[k] += __shfl_xor_sync(0xffffffffu, acc[k], 8);
        acc[k] += __shfl_xor_sync(0xffffffffu, acc[k], 16);
    }

    if (lane < 8) {
        float4* p = (float4*)(orow + (c << 3));
        p[0] = make_float4(acc[0], acc[1], acc[2], acc[3]);
        p[1] = make_float4(acc[4], acc[5], acc[6], acc[7]);
    }
}

// ---------------------------------------------------------------- launch
extern "C" void kernel_launch(void* const* d_in, const int* in_sizes, int n_in,
                              void* d_out, int out_size) {
    const float* user_feat = (const float*)d_in[0];
    const float* item_feat = (const float*)d_in[1];
    const float* norm_ui   = (const float*)d_in[2];
    const float* norm_iu   = (const float*)d_in[3];
    const int*   ui_src    = (const int*)d_in[4];
    const int*   ui_dst    = (const int*)d_in[5];
    const int*   iu_src    = (const int*)d_in[6];
    const int*   iu_dst    = (const int*)d_in[7];

    float* out = (float*)d_out;

    int n_users = in_sizes[0] / D;
    int n_items = in_sizes[1] / D;
    int E_ui    = in_sizes[4];
    int E_iu    = in_sizes[6];
    int E_total = E_ui + E_iu;
    int n_total = n_items + n_users;

    // 0. convert feature tables to half (combined table: [user | item])
    {
        int n8u = n_users * D / 8;
        int n8total = n8u + n_items * D / 8;
        k_convert<<<(n8total + 255) / 256, 256>>>((const float4*)user_feat,
                                                  (const float4*)item_feat,
                                                  n8u, n8total);
    }

    // 1. zero counts
    k_zero_counts<<<(n_total + 1 + 255) / 256, 256>>>(n_total);

    // 2. histogram over all edges (row space: [items | users])
    k_hist<<<(E_total + 255) / 256, 256>>>(ui_dst, iu_dst, E_ui, E_total, n_items);

    // 3. exclusive scan of counts -> offsets + cursor
    int nb = (n_total + SCAN_BLK - 1) / SCAN_BLK;
    k_scan_blocksums<<<nb, SCAN_BLK>>>(n_total);
    k_scan_partials<<<1, SCAN_BLK>>>(nb);
    k_scan_final<<<nb, SCAN_BLK>>>(n_total);

    // 4. reorder edges into destination buckets
    k_reorder<<<(E_total + 255) / 256, 256>>>(ui_src, ui_dst, norm_ui,
                                              iu_src, iu_dst, norm_iu,
                                              E_ui, E_total, n_items, n_users);

    // 5. gather: one warp per output row
    long long threads = (long long)n_total * 32;
    k_gather<<<(int)((threads + 255) / 256), 256>>>(out, n_items, n_users);
}